// round 1
// baseline (speedup 1.0000x reference)
#include <cuda_runtime.h>
#include <math.h>

// Problem constants
#define Dm   512
#define Hn   8
#define DKn  64
#define Sn   512
#define Bn   4
#define NTOK 2048      // B * S
#define DFFn 2048
#define Vn   32000
#define LEn  6
#define LDn  6

typedef long long ll;

// -------------------- scratch (device globals; no allocation) --------------------
__device__ float g_x  [NTOK * Dm];     // encoder state / enc_out
__device__ float g_y  [NTOK * Dm];     // decoder state
__device__ float g_q  [NTOK * Dm];
__device__ float g_k  [NTOK * Dm];
__device__ float g_v  [NTOK * Dm];
__device__ float g_ctx[NTOK * Dm];
__device__ float g_tmp[NTOK * Dm];
__device__ float g_ffn[NTOK * DFFn];
__device__ float g_attn[(size_t)Bn * Hn * Sn * Sn];

// -------------------- embedding + positional encoding --------------------
__global__ void embed_k(float* __restrict__ out, const float* __restrict__ emb,
                        const int* __restrict__ tok, const float* __restrict__ pe) {
    int t = blockIdx.x;            // 0..2047
    int s = t & (Sn - 1);
    int tk = tok[t];
    const float scale = 22.627416997969522f;  // sqrt(512)
    int base = t * Dm;
    for (int d = threadIdx.x; d < Dm; d += blockDim.x)
        out[base + d] = emb[tk * Dm + d] * scale + pe[s * Dm + d];
}

// -------------------- tiled SGEMM, NN: C = A[M,K] @ B[K,N] (+bias)(+relu) --------------------
// 64x64 tile, BK=16, 256 threads, 4x4 microtile. All dims assumed divisible.
// Batched via blockIdx.z with (b,h) decomposition: z = b*Hd + h.
__global__ void gemm_nn_k(const float* __restrict__ A, const float* __restrict__ B,
                          float* __restrict__ C, const float* __restrict__ bias,
                          int K, int lda, int ldb, int ldc,
                          ll sAb, ll sAh, ll sBb, ll sBh, ll sCb, ll sCh,
                          int Hd, int relu) {
    int z = blockIdx.z;
    int bb = z / Hd, hh = z % Hd;
    A += (ll)bb * sAb + (ll)hh * sAh;
    B += (ll)bb * sBb + (ll)hh * sBh;
    C += (ll)bb * sCb + (ll)hh * sCh;

    __shared__ float As[16][65];
    __shared__ float Bs[16][64];

    int tid = threadIdx.x;
    int tx = tid & 15, ty = tid >> 4;
    int row0 = blockIdx.y * 64, col0 = blockIdx.x * 64;

    int arow = tid >> 2;            // 0..63
    int acol = (tid & 3) * 4;       // 0,4,8,12
    int brow = tid >> 4;            // 0..15
    int bcol = (tid & 15) * 4;      // 0..60

    float acc[4][4] = {};

    for (int k0 = 0; k0 < K; k0 += 16) {
        float4 av = *(const float4*)(A + (ll)(row0 + arow) * lda + k0 + acol);
        As[acol + 0][arow] = av.x; As[acol + 1][arow] = av.y;
        As[acol + 2][arow] = av.z; As[acol + 3][arow] = av.w;
        float4 bv = *(const float4*)(B + (ll)(k0 + brow) * ldb + col0 + bcol);
        Bs[brow][bcol + 0] = bv.x; Bs[brow][bcol + 1] = bv.y;
        Bs[brow][bcol + 2] = bv.z; Bs[brow][bcol + 3] = bv.w;
        __syncthreads();
#pragma unroll
        for (int kk = 0; kk < 16; kk++) {
            float a0 = As[kk][ty * 4 + 0], a1 = As[kk][ty * 4 + 1];
            float a2 = As[kk][ty * 4 + 2], a3 = As[kk][ty * 4 + 3];
            float b0 = Bs[kk][tx * 4 + 0], b1 = Bs[kk][tx * 4 + 1];
            float b2 = Bs[kk][tx * 4 + 2], b3 = Bs[kk][tx * 4 + 3];
            acc[0][0] += a0 * b0; acc[0][1] += a0 * b1; acc[0][2] += a0 * b2; acc[0][3] += a0 * b3;
            acc[1][0] += a1 * b0; acc[1][1] += a1 * b1; acc[1][2] += a1 * b2; acc[1][3] += a1 * b3;
            acc[2][0] += a2 * b0; acc[2][1] += a2 * b1; acc[2][2] += a2 * b2; acc[2][3] += a2 * b3;
            acc[3][0] += a3 * b0; acc[3][1] += a3 * b1; acc[3][2] += a3 * b2; acc[3][3] += a3 * b3;
        }
        __syncthreads();
    }

#pragma unroll
    for (int i = 0; i < 4; i++) {
        ll rbase = (ll)(row0 + ty * 4 + i) * ldc + col0;
#pragma unroll
        for (int j = 0; j < 4; j++) {
            int c = tx * 4 + j;
            float vv = acc[i][j];
            if (bias) vv += bias[col0 + c];
            if (relu) vv = fmaxf(vv, 0.0f);
            C[rbase + c] = vv;
        }
    }
}

// -------------------- tiled SGEMM, NT: C = A[M,K] @ B[N,K]^T --------------------
__global__ void gemm_nt_k(const float* __restrict__ A, const float* __restrict__ B,
                          float* __restrict__ C,
                          int K, int lda, int ldb, int ldc,
                          ll sAb, ll sAh, ll sBb, ll sBh, ll sCb, ll sCh,
                          int Hd) {
    int z = blockIdx.z;
    int bb = z / Hd, hh = z % Hd;
    A += (ll)bb * sAb + (ll)hh * sAh;
    B += (ll)bb * sBb + (ll)hh * sBh;
    C += (ll)bb * sCb + (ll)hh * sCh;

    __shared__ float As[16][65];
    __shared__ float Bs[16][65];

    int tid = threadIdx.x;
    int tx = tid & 15, ty = tid >> 4;
    int row0 = blockIdx.y * 64, col0 = blockIdx.x * 64;

    int lrow = tid >> 2;            // 0..63
    int lcol = (tid & 3) * 4;       // 0..12

    float acc[4][4] = {};

    for (int k0 = 0; k0 < K; k0 += 16) {
        float4 av = *(const float4*)(A + (ll)(row0 + lrow) * lda + k0 + lcol);
        As[lcol + 0][lrow] = av.x; As[lcol + 1][lrow] = av.y;
        As[lcol + 2][lrow] = av.z; As[lcol + 3][lrow] = av.w;
        float4 bv = *(const float4*)(B + (ll)(col0 + lrow) * ldb + k0 + lcol);
        Bs[lcol + 0][lrow] = bv.x; Bs[lcol + 1][lrow] = bv.y;
        Bs[lcol + 2][lrow] = bv.z; Bs[lcol + 3][lrow] = bv.w;
        __syncthreads();
#pragma unroll
        for (int kk = 0; kk < 16; kk++) {
            float a0 = As[kk][ty * 4 + 0], a1 = As[kk][ty * 4 + 1];
            float a2 = As[kk][ty * 4 + 2], a3 = As[kk][ty * 4 + 3];
            float b0 = Bs[kk][tx * 4 + 0], b1 = Bs[kk][tx * 4 + 1];
            float b2 = Bs[kk][tx * 4 + 2], b3 = Bs[kk][tx * 4 + 3];
            acc[0][0] += a0 * b0; acc[0][1] += a0 * b1; acc[0][2] += a0 * b2; acc[0][3] += a0 * b3;
            acc[1][0] += a1 * b0; acc[1][1] += a1 * b1; acc[1][2] += a1 * b2; acc[1][3] += a1 * b3;
            acc[2][0] += a2 * b0; acc[2][1] += a2 * b1; acc[2][2] += a2 * b2; acc[2][3] += a2 * b3;
            acc[3][0] += a3 * b0; acc[3][1] += a3 * b1; acc[3][2] += a3 * b2; acc[3][3] += a3 * b3;
        }
        __syncthreads();
    }

#pragma unroll
    for (int i = 0; i < 4; i++) {
        ll rbase = (ll)(row0 + ty * 4 + i) * ldc + col0;
#pragma unroll
        for (int j = 0; j < 4; j++)
            C[rbase + tx * 4 + j] = acc[i][j];
    }
}

// -------------------- mask + scale + softmax over k (row length Sn) --------------------
// causal==0: valid = tok[b*Sn + k] != 0            (src mask, depends on k)
// causal==1: valid = (tok[b*Sn + q] != 0) && k<=q  (tgt mask & causal)
__global__ void softmax_k(float* __restrict__ attn, const int* __restrict__ tok,
                          float scale, int causal) {
    int q = blockIdx.x, h = blockIdx.y, b = blockIdx.z;
    float* row = attn + ((((ll)b * Hn + h) * Sn) + q) * Sn;
    int tid = threadIdx.x;
    int k0 = tid, k1 = tid + 256;

    bool qv = true;
    if (causal) qv = (tok[b * Sn + q] != 0);

    float s0 = row[k0] * scale, s1 = row[k1] * scale;
    bool m0, m1;
    if (causal) { m0 = qv && (k0 <= q); m1 = qv && (k1 <= q); }
    else        { m0 = tok[b * Sn + k0] != 0; m1 = tok[b * Sn + k1] != 0; }
    float v0 = m0 ? s0 : -1e9f;
    float v1 = m1 ? s1 : -1e9f;

    __shared__ float red[8];
    // max
    float mx = fmaxf(v0, v1);
#pragma unroll
    for (int o = 16; o; o >>= 1) mx = fmaxf(mx, __shfl_xor_sync(0xffffffffu, mx, o));
    if ((tid & 31) == 0) red[tid >> 5] = mx;
    __syncthreads();
    if (tid < 8) {
        float m = red[tid];
#pragma unroll
        for (int o = 4; o; o >>= 1) m = fmaxf(m, __shfl_xor_sync(0xffu, m, o));
        if (tid == 0) red[0] = m;
    }
    __syncthreads();
    mx = red[0];
    __syncthreads();
    // sum
    float e0 = expf(v0 - mx), e1 = expf(v1 - mx);
    float sm = e0 + e1;
#pragma unroll
    for (int o = 16; o; o >>= 1) sm += __shfl_xor_sync(0xffffffffu, sm, o);
    if ((tid & 31) == 0) red[tid >> 5] = sm;
    __syncthreads();
    if (tid < 8) {
        float m = red[tid];
#pragma unroll
        for (int o = 4; o; o >>= 1) m += __shfl_xor_sync(0xffu, m, o);
        if (tid == 0) red[0] = m;
    }
    __syncthreads();
    float inv = 1.0f / red[0];
    row[k0] = e0 * inv;
    row[k1] = e1 * inv;
}

// -------------------- residual + LayerNorm: x = LN(x + a) * g + b --------------------
__global__ void ln_res_k(float* __restrict__ x, const float* __restrict__ a,
                         const float* __restrict__ g, const float* __restrict__ be) {
    int r = blockIdx.x;
    int base = r * Dm;
    int tid = threadIdx.x;
    float v0 = x[base + tid]       + a[base + tid];
    float v1 = x[base + tid + 256] + a[base + tid + 256];

    float s = v0 + v1;
    float sq = v0 * v0 + v1 * v1;
    __shared__ float rs[8], rq[8];
#pragma unroll
    for (int o = 16; o; o >>= 1) {
        s  += __shfl_xor_sync(0xffffffffu, s, o);
        sq += __shfl_xor_sync(0xffffffffu, sq, o);
    }
    if ((tid & 31) == 0) { rs[tid >> 5] = s; rq[tid >> 5] = sq; }
    __syncthreads();
    if (tid < 8) {
        float a1 = rs[tid], a2 = rq[tid];
#pragma unroll
        for (int o = 4; o; o >>= 1) {
            a1 += __shfl_xor_sync(0xffu, a1, o);
            a2 += __shfl_xor_sync(0xffu, a2, o);
        }
        if (tid == 0) { rs[0] = a1; rq[0] = a2; }
    }
    __syncthreads();
    float mu = rs[0] * (1.0f / Dm);
    float var = rq[0] * (1.0f / Dm) - mu * mu;
    float inv = rsqrtf(var + 1e-5f);
    x[base + tid]       = g[tid]       * (v0 - mu) * inv + be[tid];
    x[base + tid + 256] = g[tid + 256] * (v1 - mu) * inv + be[tid + 256];
}

// ==================== host orchestration ====================
static void NN(const float* A, const float* B, float* C, const float* bias,
               int M, int N, int K, int lda, int ldb, int ldc, int relu) {
    dim3 grid(N / 64, M / 64, 1);
    gemm_nn_k<<<grid, 256>>>(A, B, C, bias, K, lda, ldb, ldc, 0, 0, 0, 0, 0, 0, 1, relu);
}

// Batched scores: attn[b,h,q,k] = Q[b,q,h,:] . K[b,k,h,:]
static void SCORES(const float* Q, const float* Kmat, float* attn) {
    dim3 grid(Sn / 64, Sn / 64, Bn * Hn);
    gemm_nt_k<<<grid, 256>>>(Q, Kmat, attn, DKn, Dm, Dm, Sn,
                             (ll)Sn * Dm, (ll)DKn, (ll)Sn * Dm, (ll)DKn,
                             (ll)Hn * Sn * Sn, (ll)Sn * Sn, Hn);
}

// Batched ctx: ctx[b,q,h,:] = attn[b,h,q,:] @ V[b,:,h,:]
static void CTX(const float* attn, const float* Vmat, float* ctx) {
    dim3 grid(DKn / 64, Sn / 64, Bn * Hn);
    gemm_nn_k<<<grid, 256>>>(attn, Vmat, ctx, nullptr, Sn, Sn, Dm, Dm,
                             (ll)Hn * Sn * Sn, (ll)Sn * Sn,
                             (ll)Sn * Dm, (ll)DKn,
                             (ll)Sn * Dm, (ll)DKn, Hn, 0);
}

// Full MHA: projections, scores, masked softmax, ctx, output projection -> out
static void MHA(const float* xq, const float* xkv,
                const float* w4, const float* b4,        // [4][D][D], [4][D]
                const int* mask_tok, int causal,
                float* pq, float* pk, float* pv, float* pctx, float* pattn,
                float* out) {
    NN(xq,  w4 + 0 * Dm * Dm, pq, b4 + 0 * Dm, NTOK, Dm, Dm, Dm, Dm, Dm, 0);
    NN(xkv, w4 + 1 * Dm * Dm, pk, b4 + 1 * Dm, NTOK, Dm, Dm, Dm, Dm, Dm, 0);
    NN(xkv, w4 + 2 * Dm * Dm, pv, b4 + 2 * Dm, NTOK, Dm, Dm, Dm, Dm, Dm, 0);
    SCORES(pq, pk, pattn);
    dim3 sg(Sn, Hn, Bn);
    softmax_k<<<sg, 256>>>(pattn, mask_tok, 0.125f, causal);  // 1/sqrt(64)
    CTX(pattn, pv, pctx);
    NN(pctx, w4 + 3 * Dm * Dm, out, b4 + 3 * Dm, NTOK, Dm, Dm, Dm, Dm, Dm, 0);
}

extern "C" void kernel_launch(void* const* d_in, const int* in_sizes, int n_in,
                              void* d_out, int out_size) {
    const int*   src        = (const int*)  d_in[0];
    const int*   tgt        = (const int*)  d_in[1];
    const float* enc_emb    = (const float*)d_in[2];
    const float* dec_emb    = (const float*)d_in[3];
    const float* pe         = (const float*)d_in[4];
    const float* enc_attn_w = (const float*)d_in[5];
    const float* enc_attn_b = (const float*)d_in[6];
    const float* enc_ffn_w1 = (const float*)d_in[7];
    const float* enc_ffn_b1 = (const float*)d_in[8];
    const float* enc_ffn_w2 = (const float*)d_in[9];
    const float* enc_ffn_b2 = (const float*)d_in[10];
    const float* enc_ln_g   = (const float*)d_in[11];
    const float* enc_ln_b   = (const float*)d_in[12];
    const float* dec_sa_w   = (const float*)d_in[13];
    const float* dec_sa_b   = (const float*)d_in[14];
    const float* dec_ca_w   = (const float*)d_in[15];
    const float* dec_ca_b   = (const float*)d_in[16];
    const float* dec_ffn_w1 = (const float*)d_in[17];
    const float* dec_ffn_b1 = (const float*)d_in[18];
    const float* dec_ffn_w2 = (const float*)d_in[19];
    const float* dec_ffn_b2 = (const float*)d_in[20];
    const float* dec_ln_g   = (const float*)d_in[21];
    const float* dec_ln_b   = (const float*)d_in[22];
    const float* out_w      = (const float*)d_in[23];
    const float* out_b      = (const float*)d_in[24];

    float *px, *py, *pq, *pk, *pv, *pctx, *ptmp, *pffn, *pattn;
    cudaGetSymbolAddress((void**)&px,   g_x);
    cudaGetSymbolAddress((void**)&py,   g_y);
    cudaGetSymbolAddress((void**)&pq,   g_q);
    cudaGetSymbolAddress((void**)&pk,   g_k);
    cudaGetSymbolAddress((void**)&pv,   g_v);
    cudaGetSymbolAddress((void**)&pctx, g_ctx);
    cudaGetSymbolAddress((void**)&ptmp, g_tmp);
    cudaGetSymbolAddress((void**)&pffn, g_ffn);
    cudaGetSymbolAddress((void**)&pattn, g_attn);

    // -------- encoder --------
    embed_k<<<NTOK, 256>>>(px, enc_emb, src, pe);
    for (int i = 0; i < LEn; i++) {
        const float* w4 = enc_attn_w + (ll)i * 4 * Dm * Dm;
        const float* b4 = enc_attn_b + (ll)i * 4 * Dm;
        MHA(px, px, w4, b4, src, /*causal=*/0, pq, pk, pv, pctx, pattn, ptmp);
        ln_res_k<<<NTOK, 256>>>(px, ptmp, enc_ln_g + (i * 2 + 0) * Dm, enc_ln_b + (i * 2 + 0) * Dm);
        NN(px, enc_ffn_w1 + (ll)i * Dm * DFFn, pffn, enc_ffn_b1 + i * DFFn,
           NTOK, DFFn, Dm, Dm, DFFn, DFFn, /*relu=*/1);
        NN(pffn, enc_ffn_w2 + (ll)i * DFFn * Dm, ptmp, enc_ffn_b2 + i * Dm,
           NTOK, Dm, DFFn, DFFn, Dm, Dm, 0);
        ln_res_k<<<NTOK, 256>>>(px, ptmp, enc_ln_g + (i * 2 + 1) * Dm, enc_ln_b + (i * 2 + 1) * Dm);
    }
    // px now holds enc_out (decoder reads it, never writes it)

    // -------- decoder --------
    embed_k<<<NTOK, 256>>>(py, dec_emb, tgt, pe);
    for (int i = 0; i < LDn; i++) {
        const float* sw4 = dec_sa_w + (ll)i * 4 * Dm * Dm;
        const float* sb4 = dec_sa_b + (ll)i * 4 * Dm;
        MHA(py, py, sw4, sb4, tgt, /*causal=*/1, pq, pk, pv, pctx, pattn, ptmp);
        ln_res_k<<<NTOK, 256>>>(py, ptmp, dec_ln_g + (i * 3 + 0) * Dm, dec_ln_b + (i * 3 + 0) * Dm);

        const float* cw4 = dec_ca_w + (ll)i * 4 * Dm * Dm;
        const float* cb4 = dec_ca_b + (ll)i * 4 * Dm;
        MHA(py, px, cw4, cb4, src, /*causal=*/0, pq, pk, pv, pctx, pattn, ptmp);
        ln_res_k<<<NTOK, 256>>>(py, ptmp, dec_ln_g + (i * 3 + 1) * Dm, dec_ln_b + (i * 3 + 1) * Dm);

        NN(py, dec_ffn_w1 + (ll)i * Dm * DFFn, pffn, dec_ffn_b1 + i * DFFn,
           NTOK, DFFn, Dm, Dm, DFFn, DFFn, /*relu=*/1);
        NN(pffn, dec_ffn_w2 + (ll)i * DFFn * Dm, ptmp, dec_ffn_b2 + i * Dm,
           NTOK, Dm, DFFn, DFFn, Dm, Dm, 0);
        ln_res_k<<<NTOK, 256>>>(py, ptmp, dec_ln_g + (i * 3 + 2) * Dm, dec_ln_b + (i * 3 + 2) * Dm);
    }

    // -------- final projection: [2048, 512] @ [512, 32000] + bias --------
    NN(py, out_w, (float*)d_out, out_b, NTOK, Vn, Dm, Dm, Vn, Vn, 0);
}

// round 2
// speedup vs baseline: 2.5026x; 2.5026x over previous
#include <cuda_runtime.h>
#include <math.h>

// Problem constants
#define Dm   512
#define Hn   8
#define DKn  64
#define Sn   512
#define Bn   4
#define NTOK 2048      // B * S
#define DFFn 2048
#define Vn   32000
#define LEn  6
#define LDn  6

typedef long long ll;

// -------------------- scratch (device globals; no allocation) --------------------
__device__ float g_x  [NTOK * Dm];        // encoder state / enc_out
__device__ float g_y  [NTOK * Dm];        // decoder state
__device__ float g_qkv[3 * NTOK * Dm];    // fused q,k,v
__device__ float g_ctx[NTOK * Dm];
__device__ float g_tmp[NTOK * Dm];
__device__ float g_ffn[NTOK * DFFn];
__device__ float g_attn[(size_t)Bn * Hn * Sn * Sn];

// -------------------- helpers --------------------
__device__ __forceinline__ float to_tf32(float x) {
    float y;
    asm("cvt.rna.tf32.f32 %0, %1;" : "=f"(y) : "f"(x));
    return y;
}

__device__ __forceinline__ void mma_tf32(float* d, const unsigned* a, const unsigned* b) {
    asm volatile(
        "mma.sync.aligned.m16n8k8.row.col.f32.tf32.tf32.f32 "
        "{%0,%1,%2,%3}, {%4,%5,%6,%7}, {%8,%9}, {%0,%1,%2,%3};\n"
        : "+f"(d[0]), "+f"(d[1]), "+f"(d[2]), "+f"(d[3])
        : "r"(a[0]), "r"(a[1]), "r"(a[2]), "r"(a[3]), "r"(b[0]), "r"(b[1]));
}

// ==================== TF32 tensor-core GEMM ====================
// C = A[M,K] @ B[K,N] (+bias)(+relu), B optionally transposed (B stored [N,K]).
// Block tile BM x BN, K-tile BK=16, 256 threads (8 warps, WGM x WGN layout).
// Batched over blockIdx.z with (b,h) = (z/Hd, z%Hd) stride decomposition.
// Aalt: if non-null, blocks with z>0 read A from Aalt (QKV fusion: q from xq, k/v from xkv).
template<int BM, int BN, int BK, int WGM, int WGN, bool TB, bool RELU>
__global__ void __launch_bounds__(256)
gemm_tc(const float* __restrict__ A, const float* __restrict__ Aalt,
        const float* __restrict__ B, float* __restrict__ C,
        const float* __restrict__ bias,
        int K, int lda, int ldb, int ldc,
        ll sAb, ll sAh, ll sBb, ll sBh, ll sCb, ll sCh,
        int Hd, int biasStride) {
    const int z = blockIdx.z;
    const int bb = z / Hd, hh = z % Hd;
    if (Aalt != nullptr && z > 0) A = Aalt;
    A += (ll)bb * sAb + (ll)hh * sAh;
    B += (ll)bb * sBb + (ll)hh * sBh;
    C += (ll)bb * sCb + (ll)hh * sCh;
    if (bias) bias += (ll)z * biasStride;

    const int tid = threadIdx.x;
    const int lane = tid & 31, warp = tid >> 5;
    const int wm = warp / WGN, wn = warp % WGN;
    constexpr int WTM = BM / WGM, WTN = BN / WGN;
    constexpr int MT = WTM / 16, NT = WTN / 8;
    const int row0 = blockIdx.y * BM, col0 = blockIdx.x * BN;
    const int g = lane >> 2, tg = lane & 3;

    __shared__ float As[BM][20];        // BK=16 data + pad 4 -> bank-conflict-free frags
    __shared__ float Bs[BK][BN + 8];    // pad 8 -> stride%32==8 -> conflict-free frags

    constexpr int AV = BM * BK / (256 * 4);
    constexpr int BV = BK * BN / (256 * 4);
    float4 aS[AV], bS[BV];

    auto loadG = [&](int k0) {
#pragma unroll
        for (int i = 0; i < AV; i++) {
            int t = tid + i * 256;
            int r = t / (BK / 4), kq = t % (BK / 4);
            aS[i] = *(const float4*)(A + (ll)(row0 + r) * lda + k0 + kq * 4);
        }
#pragma unroll
        for (int i = 0; i < BV; i++) {
            int t = tid + i * 256;
            if (!TB) {
                int r = t / (BN / 4), nq = t % (BN / 4);
                bS[i] = *(const float4*)(B + (ll)(k0 + r) * ldb + col0 + nq * 4);
            } else {
                int n = t / (BK / 4), kq = t % (BK / 4);
                bS[i] = *(const float4*)(B + (ll)(col0 + n) * ldb + k0 + kq * 4);
            }
        }
    };

    auto storeS = [&]() {
#pragma unroll
        for (int i = 0; i < AV; i++) {
            int t = tid + i * 256;
            int r = t / (BK / 4), kq = t % (BK / 4);
            float4 v;
            v.x = to_tf32(aS[i].x); v.y = to_tf32(aS[i].y);
            v.z = to_tf32(aS[i].z); v.w = to_tf32(aS[i].w);
            *(float4*)&As[r][kq * 4] = v;
        }
#pragma unroll
        for (int i = 0; i < BV; i++) {
            int t = tid + i * 256;
            if (!TB) {
                int r = t / (BN / 4), nq = t % (BN / 4);
                float4 v;
                v.x = to_tf32(bS[i].x); v.y = to_tf32(bS[i].y);
                v.z = to_tf32(bS[i].z); v.w = to_tf32(bS[i].w);
                *(float4*)&Bs[r][nq * 4] = v;
            } else {
                int n = t / (BK / 4), kq = t % (BK / 4);
                Bs[kq * 4 + 0][n] = to_tf32(bS[i].x);
                Bs[kq * 4 + 1][n] = to_tf32(bS[i].y);
                Bs[kq * 4 + 2][n] = to_tf32(bS[i].z);
                Bs[kq * 4 + 3][n] = to_tf32(bS[i].w);
            }
        }
    };

    float acc[MT][NT][4] = {};

    loadG(0);
    for (int k0 = 0; k0 < K; k0 += BK) {
        __syncthreads();
        storeS();
        __syncthreads();
        if (k0 + BK < K) loadG(k0 + BK);

#pragma unroll
        for (int ks = 0; ks < BK / 8; ks++) {
            const int kb = ks * 8;
            unsigned af[MT][4], bf[NT][2];
#pragma unroll
            for (int mt = 0; mt < MT; mt++) {
                int r = wm * WTM + mt * 16 + g;
                af[mt][0] = __float_as_uint(As[r][kb + tg]);
                af[mt][1] = __float_as_uint(As[r + 8][kb + tg]);
                af[mt][2] = __float_as_uint(As[r][kb + tg + 4]);
                af[mt][3] = __float_as_uint(As[r + 8][kb + tg + 4]);
            }
#pragma unroll
            for (int nt = 0; nt < NT; nt++) {
                int c = wn * WTN + nt * 8 + g;
                bf[nt][0] = __float_as_uint(Bs[kb + tg][c]);
                bf[nt][1] = __float_as_uint(Bs[kb + tg + 4][c]);
            }
#pragma unroll
            for (int mt = 0; mt < MT; mt++)
#pragma unroll
                for (int nt = 0; nt < NT; nt++)
                    mma_tf32(acc[mt][nt], af[mt], bf[nt]);
        }
    }

    // epilogue
#pragma unroll
    for (int mt = 0; mt < MT; mt++) {
#pragma unroll
        for (int nt = 0; nt < NT; nt++) {
            int r = row0 + wm * WTM + mt * 16 + g;
            int c = col0 + wn * WTN + nt * 8 + tg * 2;
            float b0 = 0.f, b1 = 0.f;
            if (bias) { b0 = bias[c]; b1 = bias[c + 1]; }
            float2 v0, v1;
            v0.x = acc[mt][nt][0] + b0; v0.y = acc[mt][nt][1] + b1;
            v1.x = acc[mt][nt][2] + b0; v1.y = acc[mt][nt][3] + b1;
            if (RELU) {
                v0.x = fmaxf(v0.x, 0.f); v0.y = fmaxf(v0.y, 0.f);
                v1.x = fmaxf(v1.x, 0.f); v1.y = fmaxf(v1.y, 0.f);
            }
            *(float2*)(C + (ll)r * ldc + c) = v0;
            *(float2*)(C + (ll)(r + 8) * ldc + c) = v1;
        }
    }
}

// -------------------- embedding + positional encoding --------------------
__global__ void embed_k(float* __restrict__ out, const float* __restrict__ emb,
                        const int* __restrict__ tok, const float* __restrict__ pe) {
    int t = blockIdx.x;
    int s = t & (Sn - 1);
    int tk = tok[t];
    const float scale = 22.627416997969522f;  // sqrt(512)
    int base = t * Dm;
    for (int d = threadIdx.x; d < Dm; d += blockDim.x)
        out[base + d] = emb[tk * Dm + d] * scale + pe[s * Dm + d];
}

// -------------------- mask + scale + softmax over k --------------------
__global__ void softmax_k(float* __restrict__ attn, const int* __restrict__ tok,
                          float scale, int causal) {
    int q = blockIdx.x, h = blockIdx.y, b = blockIdx.z;
    float* row = attn + ((((ll)b * Hn + h) * Sn) + q) * Sn;
    int tid = threadIdx.x;
    int k0 = tid, k1 = tid + 256;

    bool qv = true;
    if (causal) qv = (tok[b * Sn + q] != 0);

    float s0 = row[k0] * scale, s1 = row[k1] * scale;
    bool m0, m1;
    if (causal) { m0 = qv && (k0 <= q); m1 = qv && (k1 <= q); }
    else        { m0 = tok[b * Sn + k0] != 0; m1 = tok[b * Sn + k1] != 0; }
    float v0 = m0 ? s0 : -1e9f;
    float v1 = m1 ? s1 : -1e9f;

    __shared__ float red[8];
    float mx = fmaxf(v0, v1);
#pragma unroll
    for (int o = 16; o; o >>= 1) mx = fmaxf(mx, __shfl_xor_sync(0xffffffffu, mx, o));
    if ((tid & 31) == 0) red[tid >> 5] = mx;
    __syncthreads();
    if (tid < 8) {
        float m = red[tid];
#pragma unroll
        for (int o = 4; o; o >>= 1) m = fmaxf(m, __shfl_xor_sync(0xffu, m, o));
        if (tid == 0) red[0] = m;
    }
    __syncthreads();
    mx = red[0];
    __syncthreads();
    float e0 = expf(v0 - mx), e1 = expf(v1 - mx);
    float sm = e0 + e1;
#pragma unroll
    for (int o = 16; o; o >>= 1) sm += __shfl_xor_sync(0xffffffffu, sm, o);
    if ((tid & 31) == 0) red[tid >> 5] = sm;
    __syncthreads();
    if (tid < 8) {
        float m = red[tid];
#pragma unroll
        for (int o = 4; o; o >>= 1) m += __shfl_xor_sync(0xffu, m, o);
        if (tid == 0) red[0] = m;
    }
    __syncthreads();
    float inv = 1.0f / red[0];
    row[k0] = e0 * inv;
    row[k1] = e1 * inv;
}

// -------------------- residual + LayerNorm --------------------
__global__ void ln_res_k(float* __restrict__ x, const float* __restrict__ a,
                         const float* __restrict__ g, const float* __restrict__ be) {
    int r = blockIdx.x;
    int base = r * Dm;
    int tid = threadIdx.x;
    float v0 = x[base + tid]       + a[base + tid];
    float v1 = x[base + tid + 256] + a[base + tid + 256];

    float s = v0 + v1;
    float sq = v0 * v0 + v1 * v1;
    __shared__ float rs[8], rq[8];
#pragma unroll
    for (int o = 16; o; o >>= 1) {
        s  += __shfl_xor_sync(0xffffffffu, s, o);
        sq += __shfl_xor_sync(0xffffffffu, sq, o);
    }
    if ((tid & 31) == 0) { rs[tid >> 5] = s; rq[tid >> 5] = sq; }
    __syncthreads();
    if (tid < 8) {
        float a1 = rs[tid], a2 = rq[tid];
#pragma unroll
        for (int o = 4; o; o >>= 1) {
            a1 += __shfl_xor_sync(0xffu, a1, o);
            a2 += __shfl_xor_sync(0xffu, a2, o);
        }
        if (tid == 0) { rs[0] = a1; rq[0] = a2; }
    }
    __syncthreads();
    float mu = rs[0] * (1.0f / Dm);
    float var = rq[0] * (1.0f / Dm) - mu * mu;
    float inv = rsqrtf(var + 1e-5f);
    x[base + tid]       = g[tid]       * (v0 - mu) * inv + be[tid];
    x[base + tid + 256] = g[tid + 256] * (v1 - mu) * inv + be[tid + 256];
}

// ==================== host orchestration ====================

// Dense NN GEMM, single batch. Picks 64x128 tile for N-small shapes to keep SMs fed.
static void NN_big(const float* A, const float* B, float* C, const float* bias,
                   int M, int N, int K, int relu) {
    if (relu) {
        dim3 grid(N / 128, M / 128, 1);
        gemm_tc<128, 128, 16, 2, 4, false, true><<<grid, 256>>>(
            A, nullptr, B, C, bias, K, K, N, N, 0, 0, 0, 0, 0, 0, 1, 0);
    } else {
        dim3 grid(N / 128, M / 128, 1);
        gemm_tc<128, 128, 16, 2, 4, false, false><<<grid, 256>>>(
            A, nullptr, B, C, bias, K, K, N, N, 0, 0, 0, 0, 0, 0, 1, 0);
    }
}

static void NN_512(const float* A, const float* B, float* C, const float* bias,
                   int M, int K) {  // N = 512
    dim3 grid(Dm / 128, M / 64, 1);
    gemm_tc<64, 128, 16, 2, 4, false, false><<<grid, 256>>>(
        A, nullptr, B, C, bias, K, K, Dm, Dm, 0, 0, 0, 0, 0, 0, 1, 0);
}

// Fused QKV: z=0 -> q from xq, z=1,2 -> k,v from xkv. Weights w4[z], bias b4[z].
static void QKV(const float* xq, const float* xkv, const float* w4, const float* b4,
                float* qkv) {
    dim3 grid(Dm / 128, NTOK / 64, 3);
    gemm_tc<64, 128, 16, 2, 4, false, false><<<grid, 256>>>(
        xq, xkv, w4, qkv, b4, Dm, Dm, Dm, Dm,
        0, 0, (ll)Dm * Dm, 0, (ll)NTOK * Dm, 0, 1, Dm);
}

// Batched scores: attn[b,h,q,k] = Q[b,q,h,:] . K[b,k,h,:]   (NT)
static void SCORES(const float* Q, const float* Km, float* attn) {
    dim3 grid(Sn / 128, Sn / 128, Bn * Hn);
    gemm_tc<128, 128, 16, 2, 4, true, false><<<grid, 256>>>(
        Q, nullptr, Km, attn, nullptr, DKn, Dm, Dm, Sn,
        (ll)Sn * Dm, (ll)DKn, (ll)Sn * Dm, (ll)DKn,
        (ll)Hn * Sn * Sn, (ll)Sn * Sn, Hn, 0);
}

// Batched ctx: ctx[b,q,h,:] = attn[b,h,q,:] @ V[b,:,h,:]    (NN, N=64)
static void CTX(const float* attn, const float* Vm, float* ctx) {
    dim3 grid(DKn / 64, Sn / 128, Bn * Hn);
    gemm_tc<128, 64, 16, 4, 2, false, false><<<grid, 256>>>(
        attn, nullptr, Vm, ctx, nullptr, Sn, Sn, Dm, Dm,
        (ll)Hn * Sn * Sn, (ll)Sn * Sn, (ll)Sn * Dm, (ll)DKn,
        (ll)Sn * Dm, (ll)DKn, Hn, 0);
}

static void MHA(const float* xq, const float* xkv,
                const float* w4, const float* b4,
                const int* mask_tok, int causal,
                float* qkv, float* pctx, float* pattn, float* out) {
    float* pq = qkv;
    float* pk = qkv + (ll)NTOK * Dm;
    float* pv = qkv + 2LL * NTOK * Dm;
    QKV(xq, xkv, w4, b4, qkv);
    SCORES(pq, pk, pattn);
    dim3 sg(Sn, Hn, Bn);
    softmax_k<<<sg, 256>>>(pattn, mask_tok, 0.125f, causal);
    CTX(pattn, pv, pctx);
    NN_512(pctx, w4 + 3 * Dm * Dm, out, b4 + 3 * Dm, NTOK, Dm);
}

extern "C" void kernel_launch(void* const* d_in, const int* in_sizes, int n_in,
                              void* d_out, int out_size) {
    const int*   src        = (const int*)  d_in[0];
    const int*   tgt        = (const int*)  d_in[1];
    const float* enc_emb    = (const float*)d_in[2];
    const float* dec_emb    = (const float*)d_in[3];
    const float* pe         = (const float*)d_in[4];
    const float* enc_attn_w = (const float*)d_in[5];
    const float* enc_attn_b = (const float*)d_in[6];
    const float* enc_ffn_w1 = (const float*)d_in[7];
    const float* enc_ffn_b1 = (const float*)d_in[8];
    const float* enc_ffn_w2 = (const float*)d_in[9];
    const float* enc_ffn_b2 = (const float*)d_in[10];
    const float* enc_ln_g   = (const float*)d_in[11];
    const float* enc_ln_b   = (const float*)d_in[12];
    const float* dec_sa_w   = (const float*)d_in[13];
    const float* dec_sa_b   = (const float*)d_in[14];
    const float* dec_ca_w   = (const float*)d_in[15];
    const float* dec_ca_b   = (const float*)d_in[16];
    const float* dec_ffn_w1 = (const float*)d_in[17];
    const float* dec_ffn_b1 = (const float*)d_in[18];
    const float* dec_ffn_w2 = (const float*)d_in[19];
    const float* dec_ffn_b2 = (const float*)d_in[20];
    const float* dec_ln_g   = (const float*)d_in[21];
    const float* dec_ln_b   = (const float*)d_in[22];
    const float* out_w      = (const float*)d_in[23];
    const float* out_b      = (const float*)d_in[24];

    float *px, *py, *pqkv, *pctx, *ptmp, *pffn, *pattn;
    cudaGetSymbolAddress((void**)&px,    g_x);
    cudaGetSymbolAddress((void**)&py,    g_y);
    cudaGetSymbolAddress((void**)&pqkv,  g_qkv);
    cudaGetSymbolAddress((void**)&pctx,  g_ctx);
    cudaGetSymbolAddress((void**)&ptmp,  g_tmp);
    cudaGetSymbolAddress((void**)&pffn,  g_ffn);
    cudaGetSymbolAddress((void**)&pattn, g_attn);

    // -------- encoder --------
    embed_k<<<NTOK, 256>>>(px, enc_emb, src, pe);
    for (int i = 0; i < LEn; i++) {
        const float* w4 = enc_attn_w + (ll)i * 4 * Dm * Dm;
        const float* b4 = enc_attn_b + (ll)i * 4 * Dm;
        MHA(px, px, w4, b4, src, 0, pqkv, pctx, pattn, ptmp);
        ln_res_k<<<NTOK, 256>>>(px, ptmp, enc_ln_g + (i * 2 + 0) * Dm, enc_ln_b + (i * 2 + 0) * Dm);
        NN_big(px, enc_ffn_w1 + (ll)i * Dm * DFFn, pffn, enc_ffn_b1 + i * DFFn,
               NTOK, DFFn, Dm, 1);
        NN_512(pffn, enc_ffn_w2 + (ll)i * DFFn * Dm, ptmp, enc_ffn_b2 + i * Dm,
               NTOK, DFFn);
        ln_res_k<<<NTOK, 256>>>(px, ptmp, enc_ln_g + (i * 2 + 1) * Dm, enc_ln_b + (i * 2 + 1) * Dm);
    }

    // -------- decoder --------
    embed_k<<<NTOK, 256>>>(py, dec_emb, tgt, pe);
    for (int i = 0; i < LDn; i++) {
        const float* sw4 = dec_sa_w + (ll)i * 4 * Dm * Dm;
        const float* sb4 = dec_sa_b + (ll)i * 4 * Dm;
        MHA(py, py, sw4, sb4, tgt, 1, pqkv, pctx, pattn, ptmp);
        ln_res_k<<<NTOK, 256>>>(py, ptmp, dec_ln_g + (i * 3 + 0) * Dm, dec_ln_b + (i * 3 + 0) * Dm);

        const float* cw4 = dec_ca_w + (ll)i * 4 * Dm * Dm;
        const float* cb4 = dec_ca_b + (ll)i * 4 * Dm;
        MHA(py, px, cw4, cb4, src, 0, pqkv, pctx, pattn, ptmp);
        ln_res_k<<<NTOK, 256>>>(py, ptmp, dec_ln_g + (i * 3 + 1) * Dm, dec_ln_b + (i * 3 + 1) * Dm);

        NN_big(py, dec_ffn_w1 + (ll)i * Dm * DFFn, pffn, dec_ffn_b1 + i * DFFn,
               NTOK, DFFn, Dm, 1);
        NN_512(pffn, dec_ffn_w2 + (ll)i * DFFn * Dm, ptmp, dec_ffn_b2 + i * Dm,
               NTOK, DFFn);
        ln_res_k<<<NTOK, 256>>>(py, ptmp, dec_ln_g + (i * 3 + 2) * Dm, dec_ln_b + (i * 3 + 2) * Dm);
    }

    // -------- final projection: [2048, 512] @ [512, 32000] + bias --------
    NN_big(py, out_w, (float*)d_out, out_b, NTOK, Vn, Dm, 0);
}